// round 8
// baseline (speedup 1.0000x reference)
#include <cuda_runtime.h>
#include <cuda_bf16.h>

// WaveletTransformer_867583394320 — FINAL (machine floor, converged).
//
// Math: 4-level Haar DWT immediately inverted by its exact IDWT with the same
// detail coefficients. Haar is an orthogonal perfect-reconstruction filter
// bank: one level composes to x * 2c^2 elementwise (c = fp32(1/sqrt(2))),
// so the full pipeline is x * (2c^2)^4 = x * (1 - ~2.4e-7). Measured rel_err
// vs reference: 9.571855e-8 (threshold 1e-3). The problem is an identity =>
// optimal kernel is a pure 256 MiB device-to-device copy.
//
// Measurements (three engines, seven rounds):
//   R1  SM float4 grid-stride copy            6361 GB/s   bench 84.5us
//   R2  SM + __ldcs/__stcs + 4x MLP batching  6261 GB/s   bench 84.7us
//   R3-R7  copy-engine memcpy node (identical code):
//          84.0, 82.4, 84.5, 84.0, 83.0us  -> mean 83.6us, sigma ~0.8us
// All paths converge at ~6.4 TB/s combined R+W = ~80% of the 8 TB/s spec:
// the HBM3e read/write-turnaround floor, path-independent per
// B300_MICROARCH.md (LDG.cv ≡ TMA ≡ CE at the chip cap). Device time
// 512 MiB / 6.4 TB/s ≈ 77us; the residual ~6-7us is harness graph-replay
// overhead outside kernel control.
//
// Levers audited and closed:
//  - Traffic reduction: impossible (d_out poisoned each replay; out == in;
//    data incompressible; 256 MiB read + 256 MiB write irreducible).
//  - Inter-replay L2 persistence: needs the persisting-L2 carveout via
//    cudaDeviceSetLimit -> trips the harness "device limits changed" guard;
//    without it, a 256MB>126MB cyclic stream gets zero LRU hits.
//  - Fork-join CE+SM split: needs stream/event creation in kernel_launch
//    (determinism-rule risk) and shares the saturated DRAM controller ->
//    predicted zero gain.
//  - TMA bulk / write-through / L2-bypass stores: same path-independent cap.
//
// Final: single copy-engine memcpy node — one graph node, zero kernel-launch
// overhead, shape-agnostic, at the hardware floor.

extern "C" void kernel_launch(void* const* d_in, const int* in_sizes, int n_in,
                              void* d_out, int out_size) {
    const float* x = (const float*)d_in[0];
    float* out = (float*)d_out;
    size_t bytes = (size_t)out_size * sizeof(float);
    // Async D2D on the capture (default) stream: captured as a single memcpy
    // node executed by the copy engine. No allocation, no sync — capture-legal.
    cudaMemcpyAsync(out, x, bytes, cudaMemcpyDeviceToDevice, 0);
}

// round 10
// speedup vs baseline: 1.0069x; 1.0069x over previous
#include <cuda_runtime.h>
#include <cuda_bf16.h>

// WaveletTransformer_867583394320 — R9 probe: dual-copy-engine split.
//
// Math (established R1): 4-level Haar DWT + exact IDWT = identity to
// (2c^2)^4 ≈ 1-2.4e-7 in fp32; measured rel_err 9.57e-8 vs 1e-3 threshold.
// => pure 256 MiB D2D copy.
//
// History: SM copy 6361 GB/s; SM+streaming 6261 GB/s; single CE memcpy node
// {84.0, 82.4, 84.5, 84.0, 83.0, 84.0}us. All ~6.4 TB/s combined R+W.
// Untested hypothesis: the single CE might be engine-limited near the same
// number the SM path hits, with DRAM headroom above (tuned D2D copies reach
// ~87-90% of spec). Discriminator: fork-join capture -> TWO memcpy nodes on
// parallel graph branches -> schedulable on two CEs concurrently.
//   - If DRAM floor binds (expected): neutral, 83-85us. Hypothesis closed.
//   - If CE-limited: 73-78us.
// Streams/events are host objects (no device memory), created+destroyed
// within the call; fork is joined before destruction so the captured graph
// is just 2 memcpy nodes.

extern "C" void kernel_launch(void* const* d_in, const int* in_sizes, int n_in,
                              void* d_out, int out_size) {
    const char* x = (const char*)d_in[0];
    char* out = (char*)d_out;
    size_t bytes = (size_t)out_size * sizeof(float);
    size_t half = bytes / 2;

    cudaStream_t s2;
    cudaStreamCreateWithFlags(&s2, cudaStreamNonBlocking);
    cudaEvent_t eFork, eJoin;
    cudaEventCreateWithFlags(&eFork, cudaEventDisableTiming);
    cudaEventCreateWithFlags(&eJoin, cudaEventDisableTiming);

    // Fork: s2 depends on the head of the capture/launch stream.
    cudaEventRecord(eFork, 0);
    cudaStreamWaitEvent(s2, eFork, 0);

    // Two independent halves -> two memcpy nodes on parallel branches.
    cudaMemcpyAsync(out, x, half, cudaMemcpyDeviceToDevice, 0);
    cudaMemcpyAsync(out + half, x + half, bytes - half, cudaMemcpyDeviceToDevice, s2);

    // Join s2 back into the main stream before returning.
    cudaEventRecord(eJoin, s2);
    cudaStreamWaitEvent(0, eJoin, 0);

    // Destruction is deferred by the runtime until pending work/captures using
    // them complete; the graph retains the structure, not these handles.
    cudaEventDestroy(eFork);
    cudaEventDestroy(eJoin);
    cudaStreamDestroy(s2);
}

// round 11
// speedup vs baseline: 1.0159x; 1.0089x over previous
#include <cuda_runtime.h>
#include <cuda_bf16.h>

// WaveletTransformer_867583394320 — FINAL (machine floor; all hypotheses
// closed by measurement).
//
// Math: 4-level Haar DWT immediately inverted by its exact IDWT with the
// same detail coefficients. Haar is an orthogonal perfect-reconstruction
// filter bank: one level composes to x * 2c^2 elementwise (c = fp32(1/√2)),
// so the full pipeline is x * (2c^2)^4 = x * (1 - ~2.4e-7). Measured
// rel_err 9.571855e-8 (threshold 1e-3). The problem is an identity =>
// optimal kernel is a pure 256 MiB device-to-device copy.
//
// Full measurement record:
//   R1  SM float4 grid-stride copy            6361 GB/s   84.5us
//   R2  SM + __ldcs/__stcs + 4x MLP batching  6261 GB/s   84.7us
//   R3-R8  single CE memcpy node: {84.0, 82.4, 84.5, 84.0, 83.0, 84.0}us
//          (mean 83.7, sigma 0.8 — 82.4 is the variance tail)
//   R9  dual-CE fork-join (2 parallel memcpy nodes): 83.4us  <- NEUTRAL:
//       falsifies "single CE engine-limited"; the binding constraint is the
//       shared HBM3e mixed read/write-turnaround floor at ~6.4 TB/s (~80%
//       of 8 TB/s spec), path-independent (SM ≡ CE ≡ 2xCE, and per
//       B300_MICROARCH.md LDG.cv ≡ TMA at the chip cap).
//
// Closed levers: traffic reduction (out==in, poisoned d_out, incompressible
// data -> 512 MiB irreducible); inter-replay L2 persistence (carveout trips
// the harness device-limit guard; cyclic 256MB>126MB stream has zero LRU
// reuse without it); engine concurrency (measured neutral, R9); streaming/
// write-through/TMA paths (measured or documented at the same cap).
//
// Device time 512 MiB / 6.4 TB/s ≈ 77us; residual ~6.5us is harness
// graph-replay overhead. Final form: single memcpy node — simplest graph,
// lowest variance, at the hardware floor.

extern "C" void kernel_launch(void* const* d_in, const int* in_sizes, int n_in,
                              void* d_out, int out_size) {
    const float* x = (const float*)d_in[0];
    float* out = (float*)d_out;
    size_t bytes = (size_t)out_size * sizeof(float);
    // Async D2D on the capture (default) stream: captured as a single memcpy
    // node executed by the copy engine. No allocation, no sync — capture-legal.
    cudaMemcpyAsync(out, x, bytes, cudaMemcpyDeviceToDevice, 0);
}